// round 1
// baseline (speedup 1.0000x reference)
#include <cuda_runtime.h>
#include <math.h>

#define N_ 16384
#define D_ 2048
#define H_ 1024

// fp32(exp(-100)) = 27 * 2^-149 (subnormal), bit pattern 0x0000001B.
#define CLIP_P_BITS 27u

// ---------------- scratch (device globals; no allocation allowed) ----------
__device__ float g_x2[N_];        // ||x_n||^2
__device__ float g_mu2[H_];       // ||mu_h||^2
__device__ float g_blkmin[2048];  // per-block min of x2
__device__ float g_blkmax[128];   // per-block max of mu2
__device__ float g_z[N_];         // fallback z accumulator
__device__ float g_zconst;        // exact subnormal z for the all-clip case
__device__ int   g_flag;          // 1 => provably all power < -100

// Non-FTZ fp32 ops (immune to any -ftz / fast-math compile flags).
__device__ __forceinline__ float mul_rn(float a, float b) {
    float c; asm("mul.rn.f32 %0, %1, %2;" : "=f"(c) : "f"(a), "f"(b)); return c;
}
__device__ __forceinline__ float add_rn(float a, float b) {
    float c; asm("add.rn.f32 %0, %1, %2;" : "=f"(c) : "f"(a), "f"(b)); return c;
}

// ---------------- K1: row sums of squares for x and Mu ---------------------
// blocks 0..2047: 8 x-rows each; blocks 2048..2175: 8 Mu-rows each.
__global__ void __launch_bounds__(256) k1_sumsq(const float* __restrict__ x,
                                                const float* __restrict__ Mu) {
    __shared__ float red[8];
    const int warp = threadIdx.x >> 5;
    const int lane = threadIdx.x & 31;
    const bool isX = blockIdx.x < 2048;
    const int row  = (isX ? blockIdx.x : (blockIdx.x - 2048)) * 8 + warp;
    const float* base = isX ? x : Mu;
    const float4* r = (const float4*)(base + (size_t)row * D_);

    float s = 0.0f;
#pragma unroll
    for (int i = 0; i < 16; i++) {
        float4 v = r[lane + 32 * i];
        s += v.x * v.x + v.y * v.y + v.z * v.z + v.w * v.w;
    }
#pragma unroll
    for (int o = 16; o > 0; o >>= 1) s += __shfl_xor_sync(0xFFFFFFFFu, s, o);

    if (lane == 0) {
        if (isX) g_x2[row] = s; else g_mu2[row] = s;
        red[warp] = s;
    }
    __syncthreads();
    if (threadIdx.x == 0) {
        float m = red[0];
        if (isX) {
            for (int i = 1; i < 8; i++) m = fminf(m, red[i]);
            g_blkmin[blockIdx.x] = m;
        } else {
            for (int i = 1; i < 8; i++) m = fmaxf(m, red[i]);
            g_blkmax[blockIdx.x - 2048] = m;
        }
    }
}

// ---------------- K2: reductions + clip-bound flag + exact z ----------------
__global__ void __launch_bounds__(1024) k2_decide(const float* __restrict__ Sd,
                                                  const float* __restrict__ W) {
    __shared__ float sh[1024];
    const int t = threadIdx.x;

    // min over 2048 block-mins of x2
    sh[t] = fminf(g_blkmin[t], g_blkmin[t + 1024]);
    __syncthreads();
    for (int s = 512; s > 0; s >>= 1) {
        if (t < s) sh[t] = fminf(sh[t], sh[t + s]);
        __syncthreads();
    }
    float minx2 = sh[0];
    __syncthreads();

    // max over 128 block-maxes of mu2 (mu2 >= 0, so 0 is a safe neutral)
    sh[t] = (t < 128) ? g_blkmax[t] : 0.0f;
    __syncthreads();
    for (int s = 512; s > 0; s >>= 1) {
        if (t < s) sh[t] = fmaxf(sh[t], sh[t + s]);
        __syncthreads();
    }
    float maxmu2 = sh[0];
    __syncthreads();

    // max sd^2
    float sd = Sd[t];
    sh[t] = sd * sd;
    __syncthreads();
    for (int s = 512; s > 0; s >>= 1) {
        if (t < s) sh[t] = fmaxf(sh[t], sh[t + s]);
        __syncthreads();
    }
    float maxsd2 = sh[0];
    __syncthreads();

    // exact z for the all-clip case: z = sum_h fl(C * W[h]).
    // All products are multiples of 2^-149 and |sum| << 2^-126, so fp32
    // addition is exact and order-independent.
    const float C = __uint_as_float(CLIP_P_BITS);
    sh[t] = mul_rn(C, W[t]);
    __syncthreads();
    for (int s = 512; s > 0; s >>= 1) {
        if (t < s) sh[t] = add_rn(sh[t], sh[t + s]);
        __syncthreads();
    }

    if (t == 0) {
        g_zconst = sh[0];
        // Cauchy-Schwarz: dist(n,h) >= (sqrt(x2_n) - sqrt(mu2_h))^2 when
        // sqrt(x2_n) > sqrt(mu2_h). Need dist > 200*sd^2 for power < -100.
        // Margin covers our fp error AND the reference's fp32 GEMM rounding.
        float a = sqrtf(minx2), b = sqrtf(maxmu2);
        int flag = 0;
        if (a > b) {
            float d = a - b;
            if (d * d > 200.0f * maxsd2 * 1.001f + 4.0f) flag = 1;
        }
        g_flag = flag;
    }

    // zero fallback z accumulator (fresh every launch/replay)
    for (int i = t; i < N_; i += 1024) g_z[i] = 0.0f;
}

// ---------------- K3: write p (fast fill or correct fallback) --------------
__global__ void __launch_bounds__(256) k3_p(const float* __restrict__ x,
                                            const float* __restrict__ Mu,
                                            const float* __restrict__ Sd,
                                            const float* __restrict__ W,
                                            float* __restrict__ p) {
    if (g_flag) {
        const float C = __uint_as_float(CLIP_P_BITS);
        float4 c4 = make_float4(C, C, C, C);
        float4* p4 = (float4*)p;
        const int total = (N_ * H_) / 4;  // 4,194,304 float4
        for (int i = blockIdx.x * blockDim.x + threadIdx.x; i < total;
             i += gridDim.x * blockDim.x)
            p4[i] = c4;
    } else {
        // Correct-but-slow fallback; only runs if the clip bound fails.
        const long long total = (long long)N_ * H_;
        for (long long i = blockIdx.x * (long long)blockDim.x + threadIdx.x;
             i < total; i += (long long)gridDim.x * blockDim.x) {
            const int n = (int)(i / H_);
            const int h = (int)(i % H_);
            const float* xr = x + (size_t)n * D_;
            const float* mr = Mu + (size_t)h * D_;
            float dot = 0.0f;
            for (int k = 0; k < D_; k++) dot += xr[k] * mr[k];
            float sdv = Sd[h];
            float power = -0.5f * (g_x2[n] - 2.0f * dot + g_mu2[h]) / (sdv * sdv);
            power = fminf(fmaxf(power, -100.0f), 40.0f);
            float pv = expf(power);
            p[i] = pv;
            atomicAdd(&g_z[n], pv * W[h]);
        }
    }
}

// ---------------- K4: y = 1.7159 * tanh(2/3 * z) ---------------------------
__global__ void __launch_bounds__(256) k4_y(float* __restrict__ y) {
    const int n = blockIdx.x * blockDim.x + threadIdx.x;
    if (n >= N_) return;
    float z = g_flag ? g_zconst : g_z[n];
    float t = mul_rn(2.0f / 3.0f, z);                 // non-FTZ (z may be subnormal)
    float th = (fabsf(t) < 1e-5f) ? t : tanhf(t);     // tanh(x)==x exactly for tiny x
    y[n] = mul_rn(1.7159f, th);
}

extern "C" void kernel_launch(void* const* d_in, const int* in_sizes, int n_in,
                              void* d_out, int out_size) {
    const float* x  = (const float*)d_in[0];
    const float* Mu = (const float*)d_in[1];
    const float* Sd = (const float*)d_in[2];
    const float* W  = (const float*)d_in[3];
    float* y = (float*)d_out;          // first N_ elements
    float* p = (float*)d_out + N_;     // then N_*H_ elements

    k1_sumsq<<<2176, 256>>>(x, Mu);
    k2_decide<<<1, 1024>>>(Sd, W);
    k3_p<<<1024, 256>>>(x, Mu, Sd, W, p);
    k4_y<<<64, 256>>>(y);
}

// round 2
// speedup vs baseline: 1.1975x; 1.1975x over previous
#include <cuda_runtime.h>
#include <math.h>

#define N_ 16384
#define D_ 2048
#define H_ 1024

// fp32(exp(-100)) = 27 * 2^-149 (subnormal), bit pattern 0x0000001B.
#define CLIP_P_BITS 27u

// ---------------- scratch (device globals; no allocation allowed) ----------
__device__ float g_mu2[H_];       // ||mu_h||^2 (for fallback path)
__device__ float g_blkmax[128];   // per-block max of mu2
__device__ float g_x2thresh;      // row clips if x2 > this
__device__ float g_zconst;        // exact subnormal z for a clipped row
__device__ float g_yconst;        // y for a clipped row

// Non-FTZ fp32 ops (immune to any -ftz / fast-math compile flags).
__device__ __forceinline__ float mul_rn(float a, float b) {
    float c; asm("mul.rn.f32 %0, %1, %2;" : "=f"(c) : "f"(a), "f"(b)); return c;
}
__device__ __forceinline__ float add_rn(float a, float b) {
    float c; asm("add.rn.f32 %0, %1, %2;" : "=f"(c) : "f"(a), "f"(b)); return c;
}

// ---------------- K1: ||mu_h||^2 and per-block max --------------------------
// 128 blocks x 256 threads; warp per Mu row (8 rows/block).
__global__ void __launch_bounds__(256) k_mu(const float* __restrict__ Mu) {
    __shared__ float red[8];
    const int warp = threadIdx.x >> 5;
    const int lane = threadIdx.x & 31;
    const int row  = blockIdx.x * 8 + warp;
    const float4* r = (const float4*)(Mu + (size_t)row * D_);

    float s = 0.0f;
#pragma unroll
    for (int i = 0; i < 16; i++) {
        float4 v = r[lane + 32 * i];
        s += v.x * v.x + v.y * v.y + v.z * v.z + v.w * v.w;
    }
#pragma unroll
    for (int o = 16; o > 0; o >>= 1) s += __shfl_xor_sync(0xFFFFFFFFu, s, o);

    if (lane == 0) { g_mu2[row] = s; red[warp] = s; }
    __syncthreads();
    if (threadIdx.x == 0) {
        float m = red[0];
        for (int i = 1; i < 8; i++) m = fmaxf(m, red[i]);
        g_blkmax[blockIdx.x] = m;
    }
}

// ---------------- K2: scalars (threshold, exact z/y consts) -----------------
__global__ void __launch_bounds__(1024) k_scalar(const float* __restrict__ Sd,
                                                 const float* __restrict__ W) {
    __shared__ float sh[1024];
    const int t = threadIdx.x;

    // max mu2 over 128 block maxes (mu2 >= 0 so 0 is a safe neutral)
    sh[t] = (t < 128) ? g_blkmax[t] : 0.0f;
    __syncthreads();
    for (int s = 512; s > 0; s >>= 1) {
        if (t < s) sh[t] = fmaxf(sh[t], sh[t + s]);
        __syncthreads();
    }
    float maxmu2 = sh[0];
    __syncthreads();

    // max sd^2
    float sd = Sd[t];
    sh[t] = sd * sd;
    __syncthreads();
    for (int s = 512; s > 0; s >>= 1) {
        if (t < s) sh[t] = fmaxf(sh[t], sh[t + s]);
        __syncthreads();
    }
    float maxsd2 = sh[0];
    __syncthreads();

    // exact z for a clipped row: z = sum_h fl(C * W[h]). All products are
    // multiples of 2^-149 and |sum| << 2^-126, so fp32 addition is exact and
    // order-independent.
    const float C = __uint_as_float(CLIP_P_BITS);
    sh[t] = mul_rn(C, W[t]);
    __syncthreads();
    for (int s = 512; s > 0; s >>= 1) {
        if (t < s) sh[t] = add_rn(sh[t], sh[t + s]);
        __syncthreads();
    }

    if (t == 0) {
        float z = sh[0];
        g_zconst = z;
        float tt = mul_rn(2.0f / 3.0f, z);                // subnormal-safe
        float th = (fabsf(tt) < 1e-5f) ? tt : tanhf(tt);  // tanh(x)==x for tiny x
        g_yconst = mul_rn(1.7159f, th);

        // Row n clips for ALL h iff dist(n,h) > 200*sd_h^2 for all h.
        // Cauchy-Schwarz: dist >= (sqrt(x2) - sqrt(mu2_h))^2 when x2 > mu2_h.
        // Sufficient: sqrt(x2) > sqrt(maxmu2) + sqrt(200*maxsd2*1.001 + 4).
        // (margins cover our x2 rounding AND the reference's fp32 GEMM error)
        float rhs = sqrtf(maxmu2) + sqrtf(200.0f * maxsd2 * 1.001f + 4.0f);
        g_x2thresh = rhs * rhs;
    }
}

// ---------------- K3: fused main — read x row, prove clip, fill p, write y --
// 2048 blocks x 256 threads; warp per x row (8 rows/block).
__global__ void __launch_bounds__(256) k_main(const float* __restrict__ x,
                                              const float* __restrict__ Mu,
                                              const float* __restrict__ Sd,
                                              const float* __restrict__ W,
                                              float* __restrict__ y,
                                              float* __restrict__ p) {
    const int warp = threadIdx.x >> 5;
    const int lane = threadIdx.x & 31;
    const int n    = blockIdx.x * 8 + warp;
    const float4* xr = (const float4*)(x + (size_t)n * D_);

    float s = 0.0f;
#pragma unroll
    for (int i = 0; i < 16; i++) {
        float4 v = xr[lane + 32 * i];
        s += v.x * v.x + v.y * v.y + v.z * v.z + v.w * v.w;
    }
#pragma unroll
    for (int o = 16; o > 0; o >>= 1) s += __shfl_xor_sync(0xFFFFFFFFu, s, o);

    float4* prow = (float4*)(p + (size_t)n * H_);

    if (s > g_x2thresh) {
        // Provably all-clipped row: p[n,:] = exp(-100) exactly, y = const.
        const float C = __uint_as_float(CLIP_P_BITS);
        const float4 c4 = make_float4(C, C, C, C);
#pragma unroll
        for (int i = 0; i < 8; i++) prow[lane + 32 * i] = c4;
        if (lane == 0) y[n] = g_yconst;
    } else {
        // Correct fallback for a single unproven row (slow; insurance only).
        float z = 0.0f;
        for (int h = 0; h < H_; h++) {
            const float4* mr = (const float4*)(Mu + (size_t)h * D_);
            float dot = 0.0f;
#pragma unroll
            for (int i = 0; i < 16; i++) {
                float4 a = xr[lane + 32 * i];
                float4 b = mr[lane + 32 * i];
                dot += a.x * b.x + a.y * b.y + a.z * b.z + a.w * b.w;
            }
#pragma unroll
            for (int o = 16; o > 0; o >>= 1)
                dot += __shfl_xor_sync(0xFFFFFFFFu, dot, o);
            float sd = Sd[h];
            float power = -0.5f * (s - 2.0f * dot + g_mu2[h]) / (sd * sd);
            power = fminf(fmaxf(power, -100.0f), 40.0f);
            float pv = expf(power);
            if (lane == 0) { p[(size_t)n * H_ + h] = pv; z += pv * W[h]; }
        }
        if (lane == 0) {
            float tt = mul_rn(2.0f / 3.0f, z);
            float th = (fabsf(tt) < 1e-5f) ? tt : tanhf(tt);
            y[n] = mul_rn(1.7159f, th);
        }
    }
}

extern "C" void kernel_launch(void* const* d_in, const int* in_sizes, int n_in,
                              void* d_out, int out_size) {
    const float* x  = (const float*)d_in[0];
    const float* Mu = (const float*)d_in[1];
    const float* Sd = (const float*)d_in[2];
    const float* W  = (const float*)d_in[3];
    float* y = (float*)d_out;          // first N_ elements
    float* p = (float*)d_out + N_;     // then N_*H_ elements

    k_mu<<<128, 256>>>(Mu);
    k_scalar<<<1, 1024>>>(Sd, W);
    k_main<<<2048, 256>>>(x, Mu, Sd, W, y, p);
}

// round 3
// speedup vs baseline: 1.8410x; 1.5374x over previous
#include <cuda_runtime.h>
#include <math.h>

#define N_ 16384
#define D_ 2048
#define H_ 1024

// fp32(exp(-100)) = 27 * 2^-149 (subnormal), bit pattern 0x0000001B.
#define CLIP_P_BITS 27u

// Stage-1 reads this many leading elements of each x row (must be mult of 128).
#define S1_ELEMS 768   // 6 float4 per lane

// ---------------- scratch (device globals; no allocation allowed) ----------
__device__ float g_mu2[H_];        // ||mu_h||^2 (fallback path)
__device__ int   g_maxmu2_bits;    // atomicMax over mu2 (nonneg -> int order ok)
__device__ int   g_count;          // last-block-done counter (self-resetting)
__device__ float g_maxsd2;
__device__ float g_zconst;         // exact subnormal z for a clipped row
__device__ float g_yconst;         // y for a clipped row
__device__ float g_x2thresh;       // row clips if (partial) x2 > this

// Non-FTZ fp32 ops (immune to any -ftz / fast-math compile flags).
__device__ __forceinline__ float mul_rn(float a, float b) {
    float c; asm("mul.rn.f32 %0, %1, %2;" : "=f"(c) : "f"(a), "f"(b)); return c;
}
__device__ __forceinline__ float add_rn(float a, float b) {
    float c; asm("add.rn.f32 %0, %1, %2;" : "=f"(c) : "f"(a), "f"(b)); return c;
}

__device__ __forceinline__ float4 ldcs4(const float4* p) { return __ldcs(p); }

// ---------------- K1: prologue, fully fused ---------------------------------
// 1024 blocks x 256 threads. Block b computes mu2[b] (one Mu row).
// Block 0 additionally computes maxsd2 + exact z/y consts.
// The LAST block to finish computes the threshold and resets the scratch.
__global__ void __launch_bounds__(256) k_pre(const float* __restrict__ Mu,
                                             const float* __restrict__ Sd,
                                             const float* __restrict__ W) {
    __shared__ float sh[256];
    __shared__ float sh2[256];
    const int t = threadIdx.x;
    const int row = blockIdx.x;

    // mu2 for this row: 512 float4, 2 per thread
    const float4* r = (const float4*)(Mu + (size_t)row * D_);
    float4 a = r[t], b = r[t + 256];
    float s = a.x * a.x + a.y * a.y + a.z * a.z + a.w * a.w
            + b.x * b.x + b.y * b.y + b.z * b.z + b.w * b.w;
    sh[t] = s;
    __syncthreads();
    for (int o = 128; o > 0; o >>= 1) {
        if (t < o) sh[t] += sh[t + o];
        __syncthreads();
    }
    if (t == 0) {
        float m2 = sh[0];
        g_mu2[row] = m2;
        atomicMax(&g_maxmu2_bits, __float_as_int(m2));
    }
    __syncthreads();

    if (blockIdx.x == 0) {
        // maxsd2 over 1024 (4 per thread)
        float msd = 0.0f;
        const float C = __uint_as_float(CLIP_P_BITS);
        float zp = 0.0f;
#pragma unroll
        for (int i = 0; i < 4; i++) {
            float sd = Sd[t + 256 * i];
            msd = fmaxf(msd, sd * sd);
            // exact: all products are multiples of 2^-149, |sum| << 2^-126,
            // so fp32 adds are exact and order-independent.
            zp = add_rn(zp, mul_rn(C, W[t + 256 * i]));
        }
        sh[t] = msd;
        sh2[t] = zp;
        __syncthreads();
        for (int o = 128; o > 0; o >>= 1) {
            if (t < o) {
                sh[t] = fmaxf(sh[t], sh[t + o]);
                sh2[t] = add_rn(sh2[t], sh2[t + o]);
            }
            __syncthreads();
        }
        if (t == 0) {
            g_maxsd2 = sh[0];
            float z = sh2[0];
            g_zconst = z;
            float tt = mul_rn(2.0f / 3.0f, z);                // subnormal-safe
            float th = (fabsf(tt) < 1e-5f) ? tt : tanhf(tt);  // tanh(x)==x tiny
            g_yconst = mul_rn(1.7159f, th);
        }
        __syncthreads();
    }

    if (t == 0) {
        __threadfence();
        int c = atomicAdd(&g_count, 1);
        if (c == (int)gridDim.x - 1) {   // last block done
            __threadfence();
            float maxmu2 = __int_as_float(g_maxmu2_bits);
            float maxsd2 = g_maxsd2;
            // Row n clips for ALL h iff dist(n,h) > 200*sd_h^2 for all h.
            // Cauchy-Schwarz: dist >= (sqrt(x2)-sqrt(mu2_h))^2 when x2>mu2_h.
            // Margins cover our fp error AND the reference's fp32 GEMM error.
            float rhs = sqrtf(maxmu2) + sqrtf(200.0f * maxsd2 * 1.001f + 4.0f);
            g_x2thresh = rhs * rhs;
            // reset for next graph replay
            g_maxmu2_bits = 0;
            g_count = 0;
            __threadfence();
        }
    }
}

// ---------------- K2: fused main --------------------------------------------
// 2048 blocks x 256 threads; warp per x row. Stage 1 reads only the first
// S1_ELEMS elements (a LOWER BOUND on x2 -- sums of squares are monotone).
// If the bound already beats the threshold, fill p row + y without reading
// the rest of x. Otherwise extend to the exact x2; only if that still fails
// does the exact (slow) fallback run.
__global__ void __launch_bounds__(256) k_main(const float* __restrict__ x,
                                              const float* __restrict__ Mu,
                                              const float* __restrict__ Sd,
                                              const float* __restrict__ W,
                                              float* __restrict__ y,
                                              float* __restrict__ p) {
    const int warp = threadIdx.x >> 5;
    const int lane = threadIdx.x & 31;
    const int n    = blockIdx.x * 8 + warp;
    const float4* xr = (const float4*)(x + (size_t)n * D_);
    const float thresh = g_x2thresh;

    // Stage 1: 6 independent float4 loads per lane (768 elems total)
    float4 v[6];
#pragma unroll
    for (int i = 0; i < 6; i++) v[i] = ldcs4(xr + lane + 32 * i);
    float s = 0.0f;
#pragma unroll
    for (int i = 0; i < 6; i++)
        s += v[i].x * v[i].x + v[i].y * v[i].y + v[i].z * v[i].z + v[i].w * v[i].w;
#pragma unroll
    for (int o = 16; o > 0; o >>= 1) s += __shfl_xor_sync(0xFFFFFFFFu, s, o);

    bool clipped = (s > thresh);
    if (!clipped) {
        // Stage 2: read the remaining 1280 elems for the exact x2.
        float s2 = 0.0f;
#pragma unroll
        for (int i = 6; i < 16; i++) {
            float4 w4 = ldcs4(xr + lane + 32 * i);
            s2 += w4.x * w4.x + w4.y * w4.y + w4.z * w4.z + w4.w * w4.w;
        }
#pragma unroll
        for (int o = 16; o > 0; o >>= 1) s2 += __shfl_xor_sync(0xFFFFFFFFu, s2, o);
        s += s2;
        clipped = (s > thresh);
    }

    float4* prow = (float4*)(p + (size_t)n * H_);

    if (clipped) {
        const float C = __uint_as_float(CLIP_P_BITS);
        const float4 c4 = make_float4(C, C, C, C);
#pragma unroll
        for (int i = 0; i < 8; i++) __stcs(prow + lane + 32 * i, c4);
        if (lane == 0) y[n] = g_yconst;
    } else {
        // Exact fallback for an unproven row (insurance; ~never runs).
        float z = 0.0f;
        for (int h = 0; h < H_; h++) {
            const float4* mr = (const float4*)(Mu + (size_t)h * D_);
            float dot = 0.0f;
#pragma unroll
            for (int i = 0; i < 16; i++) {
                float4 a4 = xr[lane + 32 * i];
                float4 b4 = mr[lane + 32 * i];
                dot += a4.x * b4.x + a4.y * b4.y + a4.z * b4.z + a4.w * b4.w;
            }
#pragma unroll
            for (int o = 16; o > 0; o >>= 1)
                dot += __shfl_xor_sync(0xFFFFFFFFu, dot, o);
            float sd = Sd[h];
            float power = -0.5f * (s - 2.0f * dot + g_mu2[h]) / (sd * sd);
            power = fminf(fmaxf(power, -100.0f), 40.0f);
            float pv = expf(power);
            if (lane == 0) { p[(size_t)n * H_ + h] = pv; z += pv * W[h]; }
        }
        if (lane == 0) {
            float tt = mul_rn(2.0f / 3.0f, z);
            float th = (fabsf(tt) < 1e-5f) ? tt : tanhf(tt);
            y[n] = mul_rn(1.7159f, th);
        }
    }
}

extern "C" void kernel_launch(void* const* d_in, const int* in_sizes, int n_in,
                              void* d_out, int out_size) {
    const float* x  = (const float*)d_in[0];
    const float* Mu = (const float*)d_in[1];
    const float* Sd = (const float*)d_in[2];
    const float* W  = (const float*)d_in[3];
    float* y = (float*)d_out;          // first N_ elements
    float* p = (float*)d_out + N_;     // then N_*H_ elements

    k_pre<<<1024, 256>>>(Mu, Sd, W);
    k_main<<<2048, 256>>>(x, Mu, Sd, W, y, p);
}